// round 2
// baseline (speedup 1.0000x reference)
#include <cuda_runtime.h>
#include <cstdint>

// ---------------------------------------------------------------------------
// Sparse 3x3x3 conv chain, N=1e6 voxels, avg ~2.55 active taps/voxel.
// Strategy: build per-voxel compact (k,src) lists once; 6 warp-per-voxel conv
// kernels with W in shared (transposed, padded rows -> conflict-free LDS).
// tile() folded into Wd0; residual and final add fused into conv epilogues.
// neighbor_mask arrives as bool -> unknown wire dtype; detect on device.
// ---------------------------------------------------------------------------

#define MAXN 1000000
#define NSM  148

__device__ int   g_mtype;                  // 0=int32, 1=uint8, 2=float32
__device__ int   g_cnt[MAXN];
__device__ int   g_list[MAXN * 27];        // packed (k<<20)|src
__device__ float g_t32[(size_t)MAXN * 32];
__device__ float g_t8a[(size_t)MAXN * 8];
__device__ float g_t8b[(size_t)MAXN * 8];
__device__ float g_wfold[27 * 8 * 32];

// ---------------------------------------------------------------------------
// Mask wire-dtype detection. Bool arrays may be shipped as int32 (values 0/1),
// uint8 (packed bytes 0/1 -> words like 0x00010001 > 1), or float32 (0 /
// 0x3F800000). Scan 64K words; classification is deterministic for this data.
__global__ void detect_mask(const unsigned int* __restrict__ m) {
    __shared__ int s_u8, s_f32;
    if (threadIdx.x == 0) { s_u8 = 0; s_f32 = 0; }
    __syncthreads();
    int loc_u8 = 0, loc_f32 = 0;
    for (int i = threadIdx.x; i < 65536; i += blockDim.x) {
        unsigned v = m[i];
        if (v == 0x3F800000u)      loc_f32 = 1;
        else if (v > 1u)           loc_u8 = 1;
    }
    if (loc_u8)  atomicOr(&s_u8, 1);
    if (loc_f32) atomicOr(&s_f32, 1);
    __syncthreads();
    if (threadIdx.x == 0) g_mtype = s_f32 ? 2 : (s_u8 ? 1 : 0);
}

// ---------------------------------------------------------------------------
__global__ void build_compact(const int* __restrict__ nbr,
                              const void* __restrict__ maskv, int N) {
    int n = blockIdx.x * blockDim.x + threadIdx.x;
    if (n >= N) return;
    const int mt = g_mtype;
    const int*           mi = (const int*)maskv;
    const unsigned char* mb = (const unsigned char*)maskv;
    const float*         mf = (const float*)maskv;
    int cnt = 0;
    int* lst = &g_list[n * 27];
#pragma unroll 1
    for (int k = 0; k < 27; k++) {
        size_t o = (size_t)k * N + n;
        bool on;
        if (mt == 0)      on = mi[o] != 0;
        else if (mt == 1) on = mb[o] != 0;
        else              on = mf[o] != 0.0f;
        if (on) {
            int idx = nbr[o];
            lst[cnt++] = (k << 20) | idx;
        }
    }
    g_cnt[n] = cnt;
}

// Fold tile(x,(1,4)) into Wd0: wfold[k][c][j] = sum_t Wd0[k][c+8t][j]
__global__ void fold_wd0(const float* __restrict__ Wd0) {
    int i = blockIdx.x * blockDim.x + threadIdx.x;
    if (i >= 27 * 8 * 32) return;
    int k = i / 256, rem = i % 256;
    int c = rem / 32, j = rem % 32;
    float s = 0.f;
#pragma unroll
    for (int t = 0; t < 4; t++) s += Wd0[k * 1024 + (c + 8 * t) * 32 + j];
    g_wfold[i] = s;
}

// ---------------------------------------------------------------------------
// Generic sparse conv, warp-per-voxel.
//   COUT==32: lane j = output channel, covers all CIN.
//   COUT==8 : lane -> (oc = lane&7, Cin slice lane>>3), shfl_xor reduce.
// W in SMEM transposed [27][COUT][R], R=CIN+1 (bank-conflict-free scalar LDS).
// EPI: 0 none; 1: out = xres - conv (8ch); 2: out = tile(xres) + conv (32ch).
// ---------------------------------------------------------------------------
template <int CIN, int COUT, int EPI>
__global__ void conv_kernel(const float* __restrict__ in,
                            const float* __restrict__ W,
                            const float* __restrict__ xres,
                            float* __restrict__ out, int N) {
    constexpr int R = CIN + 1;
    extern __shared__ float Ws[];  // [27][COUT][R]

    const int tid = threadIdx.x;
    for (int i = tid; i < 27 * CIN * COUT; i += blockDim.x) {
        int k = i / (CIN * COUT);
        int rem = i % (CIN * COUT);
        int c = rem / COUT, j = rem % COUT;
        Ws[(k * COUT + j) * R + c] = W[i];
    }
    __syncthreads();

    const int lane = tid & 31;
    const int warp = tid >> 5;
    const int wpb  = blockDim.x >> 5;

    int oc, cs0;
    constexpr int csn = (COUT == 32) ? CIN : (CIN / 4);
    if (COUT == 32) { oc = lane; cs0 = 0; }
    else            { oc = lane & 7; cs0 = (lane >> 3) * csn; }

    for (int n = blockIdx.x * wpb + warp; n < N; n += gridDim.x * wpb) {
        const int cnt = g_cnt[n];
        const int* lst = &g_list[n * 27];
        float acc = 0.f;
#pragma unroll 1
        for (int i = 0; i < cnt; i++) {
            const int e   = lst[i];
            const int k   = e >> 20;
            const int src = e & 0xFFFFF;
            const float* grow = &in[(size_t)src * CIN + cs0];
            const float* wrow = &Ws[(k * COUT + oc) * R + cs0];
            if constexpr ((csn & 3) == 0) {
#pragma unroll
                for (int c = 0; c < csn; c += 4) {
                    float4 g = *reinterpret_cast<const float4*>(grow + c);
                    acc += g.x * wrow[c + 0];
                    acc += g.y * wrow[c + 1];
                    acc += g.z * wrow[c + 2];
                    acc += g.w * wrow[c + 3];
                }
            } else {
#pragma unroll
                for (int c = 0; c < csn; c++) acc += grow[c] * wrow[c];
            }
        }
        if constexpr (COUT == 8) {
            acc += __shfl_xor_sync(0xffffffffu, acc, 8);
            acc += __shfl_xor_sync(0xffffffffu, acc, 16);
            if (lane < 8) {
                float v = acc;
                if constexpr (EPI == 1) v = xres[(size_t)n * 8 + lane] - v;
                out[(size_t)n * 8 + lane] = v;
            }
        } else {
            float v = acc;
            if constexpr (EPI == 2) v += xres[(size_t)n * 8 + (lane & 7)];
            out[(size_t)n * 32 + lane] = v;
        }
    }
}

// ---------------------------------------------------------------------------
extern "C" void kernel_launch(void* const* d_in, const int* in_sizes, int n_in,
                              void* d_out, int out_size) {
    const float* x    = (const float*)d_in[0];
    const int*   nbr  = (const int*)d_in[1];
    const void*  mask = (const void*)d_in[2];
    const float* Wd0  = (const float*)d_in[3];
    const float* Wd1  = (const float*)d_in[4];
    const float* Wd2  = (const float*)d_in[5];
    const float* Wu0  = (const float*)d_in[6];
    const float* Wu1  = (const float*)d_in[7];
    const float* Wu2  = (const float*)d_in[8];
    float*       out  = (float*)d_out;
    const int N = in_sizes[0] / 8;

    float *t32, *t8a, *t8b, *wfold;
    cudaGetSymbolAddress((void**)&t32,   g_t32);
    cudaGetSymbolAddress((void**)&t8a,   g_t8a);
    cudaGetSymbolAddress((void**)&t8b,   g_t8b);
    cudaGetSymbolAddress((void**)&wfold, g_wfold);

    const int smem_8_32  = 27 * 32 * 9  * 4;   // 31,104 B
    const int smem_32_8  = 27 * 8  * 33 * 4;   // 28,512 B
    const int smem_8_8   = 27 * 8  * 9  * 4;   //  7,776 B
    const int smem_32_32 = 27 * 32 * 33 * 4;   // 114,048 B

    cudaFuncSetAttribute(conv_kernel<32, 32, 2>,
                         cudaFuncAttributeMaxDynamicSharedMemorySize,
                         smem_32_32);

    detect_mask<<<1, 256>>>((const unsigned int*)mask);
    build_compact<<<(N + 255) / 256, 256>>>(nbr, mask, N);
    fold_wd0<<<(27 * 8 * 32 + 255) / 256, 256>>>(Wd0);

    const int grid2 = NSM * 2;  // persistent, 2 CTAs/SM of 1024 threads

    // K1: conv(tile(x), Wd0) == conv(x, wfold)   8 -> 32
    conv_kernel<8, 32, 0><<<grid2, 1024, smem_8_32>>>(x, wfold, x, t32, N);
    // K2: 32 -> 8
    conv_kernel<32, 8, 0><<<grid2, 1024, smem_32_8>>>(t32, Wd1, x, t8a, N);
    // K3: 8 -> 8, epilogue r0 = x - d
    conv_kernel<8, 8, 1><<<grid2, 1024, smem_8_8>>>(t8a, Wd2, x, t8b, N);
    // K4: 8 -> 8
    conv_kernel<8, 8, 0><<<grid2, 1024, smem_8_8>>>(t8b, Wu0, x, t8a, N);
    // K5: 8 -> 32
    conv_kernel<8, 32, 0><<<grid2, 1024, smem_8_32>>>(t8a, Wu1, x, t32, N);
    // K6: 32 -> 32, epilogue out = tile(x) + conv   (114 KB smem -> 1 CTA/SM)
    conv_kernel<32, 32, 2><<<NSM, 1024, smem_32_32>>>(t32, Wu2, x, out, N);
}

// round 4
// speedup vs baseline: 1.0568x; 1.0568x over previous
#include <cuda_runtime.h>
#include <cstdint>

// ---------------------------------------------------------------------------
// Sparse 3x3x3 conv chain, N=1e6 voxels.  Center tap (k=13, always active,
// src=n) densified — weights in registers, no list/LDS traffic (39% of all
// entries).  Off-center entries (~1.55/voxel) use float4 LDS from padded SMEM
// (R = CIN+4 -> 16B-aligned rows, conflict-light) with 4 split accumulators.
// R4 fix: <32,8> config also gets R=36 (R=33 rows broke LDS.128 alignment).
// ---------------------------------------------------------------------------

#define MAXN 1000000
#define NSM  148

__device__ int   g_mtype;                  // 0=int32, 1=uint8, 2=float32
__device__ int   g_cnt[MAXN];
__device__ int   g_list[MAXN * 27];        // packed (k<<20)|src, k != 13
__device__ float g_t32[(size_t)MAXN * 32];
__device__ float g_t8a[(size_t)MAXN * 8];
__device__ float g_t8b[(size_t)MAXN * 8];
__device__ float g_wfold[27 * 8 * 32];

// ---------------------------------------------------------------------------
__global__ void detect_mask(const unsigned int* __restrict__ m) {
    __shared__ int s_u8, s_f32;
    if (threadIdx.x == 0) { s_u8 = 0; s_f32 = 0; }
    __syncthreads();
    int loc_u8 = 0, loc_f32 = 0;
    for (int i = threadIdx.x; i < 65536; i += blockDim.x) {
        unsigned v = m[i];
        if (v == 0x3F800000u) loc_f32 = 1;
        else if (v > 1u)      loc_u8 = 1;
    }
    if (loc_u8)  atomicOr(&s_u8, 1);
    if (loc_f32) atomicOr(&s_f32, 1);
    __syncthreads();
    if (threadIdx.x == 0) g_mtype = s_f32 ? 2 : (s_u8 ? 1 : 0);
}

// Build off-center compact lists (k == 13 handled densely in conv kernels).
__global__ void build_compact(const int* __restrict__ nbr,
                              const void* __restrict__ maskv, int N) {
    int n = blockIdx.x * blockDim.x + threadIdx.x;
    if (n >= N) return;
    const int mt = g_mtype;
    const int*           mi = (const int*)maskv;
    const unsigned char* mb = (const unsigned char*)maskv;
    const float*         mf = (const float*)maskv;
    int cnt = 0;
    int* lst = &g_list[n * 27];
#pragma unroll 1
    for (int k = 0; k < 27; k++) {
        if (k == 13) continue;
        size_t o = (size_t)k * N + n;
        bool on;
        if (mt == 0)      on = mi[o] != 0;
        else if (mt == 1) on = mb[o] != 0;
        else              on = mf[o] != 0.0f;
        if (on) lst[cnt++] = (k << 20) | nbr[o];
    }
    g_cnt[n] = cnt;
}

// Fold tile(x,(1,4)) into Wd0: wfold[k][c][j] = sum_t Wd0[k][c+8t][j]
__global__ void fold_wd0(const float* __restrict__ Wd0) {
    int i = blockIdx.x * blockDim.x + threadIdx.x;
    if (i >= 27 * 8 * 32) return;
    int k = i / 256, rem = i % 256;
    int c = rem / 32, j = rem % 32;
    float s = 0.f;
#pragma unroll
    for (int t = 0; t < 4; t++) s += Wd0[k * 1024 + (c + 8 * t) * 32 + j];
    g_wfold[i] = s;
}

// ---------------------------------------------------------------------------
// Warp-per-voxel sparse conv with dense center tap.
//  COUT==32: lane = oc, full CIN per lane.
//  COUT==8 : lane -> (oc=lane&7, Cin slice lane>>3), shfl_xor reduce.
// SMEM weight layout [27][COUT][R], R = CIN+4 when the per-lane Cin slice is a
// multiple of 4 (16B-aligned rows for LDS.128), else CIN+1 (scalar path).
// EPI: 0 none; 1: out = xres - conv (8ch); 2: out = tile(xres) + conv (32ch).
// ---------------------------------------------------------------------------
template <int CIN, int COUT, int EPI, int TB, int MINB>
__global__ void __launch_bounds__(TB, MINB)
conv_kernel(const float* __restrict__ in,
            const float* __restrict__ W,
            const float* __restrict__ xres,
            float* __restrict__ out, int N) {
    constexpr int csn = (COUT == 32) ? CIN : (CIN / 4);
    constexpr bool V4 = (csn & 3) == 0;
    constexpr int R   = V4 ? (CIN + 4) : (CIN + 1);
    extern __shared__ float Ws[];  // [27][COUT][R]

    const int tid = threadIdx.x;
    for (int i = tid; i < 27 * CIN * COUT; i += blockDim.x) {
        int k = i / (CIN * COUT);
        int rem = i % (CIN * COUT);
        int c = rem / COUT, j = rem % COUT;
        Ws[(k * COUT + j) * R + c] = W[i];
    }
    __syncthreads();

    const int lane = tid & 31;
    const int warp = tid >> 5;
    const int wpb  = blockDim.x >> 5;

    int oc, cs0;
    if (COUT == 32) { oc = lane; cs0 = 0; }
    else            { oc = lane & 7; cs0 = (lane >> 3) * csn; }

    // center-tap weights in registers: wc[c] = W[13][cs0+c][oc]
    float wc[csn];
#pragma unroll
    for (int c = 0; c < csn; c++)
        wc[c] = W[(13 * CIN + cs0 + c) * COUT + oc];

    for (int n = blockIdx.x * wpb + warp; n < N; n += gridDim.x * wpb) {
        const float* xr = &in[(size_t)n * CIN];
        float acc0 = 0.f, acc1 = 0.f, acc2 = 0.f, acc3 = 0.f;

        // ---- dense center tap, weights from registers ----
        if constexpr (V4) {
            const float4* x4 = reinterpret_cast<const float4*>(xr + cs0);
#pragma unroll
            for (int c = 0; c < csn / 4; c++) {
                float4 g = x4[c];
                acc0 += g.x * wc[4 * c + 0];
                acc1 += g.y * wc[4 * c + 1];
                acc2 += g.z * wc[4 * c + 2];
                acc3 += g.w * wc[4 * c + 3];
            }
        } else {
#pragma unroll
            for (int c = 0; c < csn; c++) acc0 += xr[cs0 + c] * wc[c];
        }

        // ---- off-center entries ----
        const int cnt = g_cnt[n];
        const int* lst = &g_list[n * 27];
#pragma unroll 1
        for (int i = 0; i < cnt; i++) {
            const int e   = lst[i];
            const int k   = e >> 20;
            const int src = e & 0xFFFFF;
            const float* grow = &in[(size_t)src * CIN + cs0];
            const float* wrow = &Ws[(k * COUT + oc) * R + cs0];
            if constexpr (V4) {
                const float4* g4 = reinterpret_cast<const float4*>(grow);
                const float4* w4 = reinterpret_cast<const float4*>(wrow);
#pragma unroll
                for (int c = 0; c < csn / 4; c++) {
                    float4 g = g4[c];
                    float4 w = w4[c];
                    acc0 += g.x * w.x;
                    acc1 += g.y * w.y;
                    acc2 += g.z * w.z;
                    acc3 += g.w * w.w;
                }
            } else {
#pragma unroll
                for (int c = 0; c < csn; c++) acc0 += grow[c] * wrow[c];
            }
        }
        float acc = (acc0 + acc1) + (acc2 + acc3);

        if constexpr (COUT == 8) {
            acc += __shfl_xor_sync(0xffffffffu, acc, 8);
            acc += __shfl_xor_sync(0xffffffffu, acc, 16);
            if (lane < 8) {
                float v = acc;
                if constexpr (EPI == 1) v = xres[(size_t)n * 8 + lane] - v;
                out[(size_t)n * 8 + lane] = v;
            }
        } else {
            float v = acc;
            if constexpr (EPI == 2) v += xres[(size_t)n * 8 + (lane & 7)];
            out[(size_t)n * 32 + lane] = v;
        }
    }
}

// ---------------------------------------------------------------------------
extern "C" void kernel_launch(void* const* d_in, const int* in_sizes, int n_in,
                              void* d_out, int out_size) {
    const float* x    = (const float*)d_in[0];
    const int*   nbr  = (const int*)d_in[1];
    const void*  mask = (const void*)d_in[2];
    const float* Wd0  = (const float*)d_in[3];
    const float* Wd1  = (const float*)d_in[4];
    const float* Wd2  = (const float*)d_in[5];
    const float* Wu0  = (const float*)d_in[6];
    const float* Wu1  = (const float*)d_in[7];
    const float* Wu2  = (const float*)d_in[8];
    float*       out  = (float*)d_out;
    const int N = in_sizes[0] / 8;

    float *t32, *t8a, *t8b, *wfold;
    cudaGetSymbolAddress((void**)&t32,   g_t32);
    cudaGetSymbolAddress((void**)&t8a,   g_t8a);
    cudaGetSymbolAddress((void**)&t8b,   g_t8b);
    cudaGetSymbolAddress((void**)&wfold, g_wfold);

    const int smem_8_32  = 27 * 32 * 12 * 4;   //  41,472 B (R=12)
    const int smem_32_8  = 27 * 8  * 36 * 4;   //  31,104 B (R=36)
    const int smem_8_8   = 27 * 8  * 9  * 4;   //   7,776 B (R=9)
    const int smem_32_32 = 27 * 32 * 36 * 4;   // 124,416 B (R=36)

    cudaFuncSetAttribute((const void*)conv_kernel<32, 32, 2, 768, 1>,
                         cudaFuncAttributeMaxDynamicSharedMemorySize,
                         smem_32_32);

    detect_mask<<<1, 256>>>((const unsigned int*)mask);
    build_compact<<<(N + 255) / 256, 256>>>(nbr, mask, N);
    fold_wd0<<<(27 * 8 * 32 + 255) / 256, 256>>>(Wd0);

    // K1: conv(tile(x), Wd0) == conv(x, wfold)   8 -> 32
    conv_kernel<8, 32, 0, 512, 3><<<NSM * 3, 512, smem_8_32>>>(x, wfold, x, t32, N);
    // K2: 32 -> 8
    conv_kernel<32, 8, 0, 512, 3><<<NSM * 3, 512, smem_32_8>>>(t32, Wd1, x, t8a, N);
    // K3: 8 -> 8, epilogue r0 = x - d
    conv_kernel<8, 8, 1, 512, 4><<<NSM * 4, 512, smem_8_8>>>(t8a, Wd2, x, t8b, N);
    // K4: 8 -> 8
    conv_kernel<8, 8, 0, 512, 4><<<NSM * 4, 512, smem_8_8>>>(t8b, Wu0, x, t8a, N);
    // K5: 8 -> 32
    conv_kernel<8, 32, 0, 512, 3><<<NSM * 3, 512, smem_8_32>>>(t8a, Wu1, x, t32, N);
    // K6: 32 -> 32, epilogue out = tile(x) + conv   (124 KB smem -> 1 CTA/SM)
    conv_kernel<32, 32, 2, 768, 1><<<NSM, 768, smem_32_32>>>(t32, Wu2, x, out, N);
}

// round 5
// speedup vs baseline: 1.1352x; 1.0742x over previous
#include <cuda_runtime.h>
#include <cstdint>

// ---------------------------------------------------------------------------
// Sparse 3x3x3 conv chain, N=1e6 voxels. R5: latency-bound fix —
//  * cnt packed into list entry0 bits[27:32), list stride 28 (16B aligned)
//    -> one speculative int4 LDG covers cnt<=4 (98.7% of voxels)
//  * ILP=2 voxels per warp iteration (batched list loads, 2 indep chains)
//  * per-kernel occupancy tuning (256-thr blocks, high MINB; K6 1024-thr)
// Center tap (k=13) stays densified in registers.
// ---------------------------------------------------------------------------

#define MAXN 1000000
#define NSM  148
#define LSTR 28   // per-voxel list stride (ints), 112B -> int4-aligned

__device__ int   g_mtype;                  // 0=int32, 1=uint8, 2=float32
__device__ int   g_list[(size_t)MAXN * LSTR];
__device__ float g_t32[(size_t)MAXN * 32];
__device__ float g_t8a[(size_t)MAXN * 8];
__device__ float g_t8b[(size_t)MAXN * 8];
__device__ float g_wfold[27 * 8 * 32];

// ---------------------------------------------------------------------------
__global__ void detect_mask(const unsigned int* __restrict__ m) {
    __shared__ int s_u8, s_f32;
    if (threadIdx.x == 0) { s_u8 = 0; s_f32 = 0; }
    __syncthreads();
    int loc_u8 = 0, loc_f32 = 0;
    for (int i = threadIdx.x; i < 65536; i += blockDim.x) {
        unsigned v = m[i];
        if (v == 0x3F800000u) loc_f32 = 1;
        else if (v > 1u)      loc_u8 = 1;
    }
    if (loc_u8)  atomicOr(&s_u8, 1);
    if (loc_f32) atomicOr(&s_f32, 1);
    __syncthreads();
    if (threadIdx.x == 0) g_mtype = s_f32 ? 2 : (s_u8 ? 1 : 0);
}

// Off-center entries only (k==13 handled densely). entry = (k<<20)|src,
// entry0 additionally carries cnt in bits [27:32).
__global__ void build_compact(const int* __restrict__ nbr,
                              const void* __restrict__ maskv, int N) {
    int n = blockIdx.x * blockDim.x + threadIdx.x;
    if (n >= N) return;
    const int mt = g_mtype;
    const int*           mi = (const int*)maskv;
    const unsigned char* mb = (const unsigned char*)maskv;
    const float*         mf = (const float*)maskv;
    int cnt = 0, first = 0;
    int* lst = &g_list[(size_t)n * LSTR];
#pragma unroll 1
    for (int k = 0; k < 27; k++) {
        if (k == 13) continue;
        size_t o = (size_t)k * N + n;
        bool on;
        if (mt == 0)      on = mi[o] != 0;
        else if (mt == 1) on = mb[o] != 0;
        else              on = mf[o] != 0.0f;
        if (on) {
            int e = (k << 20) | nbr[o];
            if (cnt == 0) first = e;
            else          lst[cnt] = e;
            cnt++;
        }
    }
    lst[0] = first | (cnt << 27);
    if (cnt < 2) lst[1] = 0;
    if (cnt < 3) lst[2] = 0;
    if (cnt < 4) lst[3] = 0;
}

// Fold tile(x,(1,4)) into Wd0: wfold[k][c][j] = sum_t Wd0[k][c+8t][j]
__global__ void fold_wd0(const float* __restrict__ Wd0) {
    int i = blockIdx.x * blockDim.x + threadIdx.x;
    if (i >= 27 * 8 * 32) return;
    int k = i / 256, rem = i % 256;
    int c = rem / 32, j = rem % 32;
    float s = 0.f;
#pragma unroll
    for (int t = 0; t < 4; t++) s += Wd0[k * 1024 + (c + 8 * t) * 32 + j];
    g_wfold[i] = s;
}

// ---------------------------------------------------------------------------
// Warp-per-voxel (x ILP) sparse conv with dense center tap.
//  COUT==32: lane = oc, full CIN per lane.
//  COUT==8 : lane -> (oc=lane&7, Cin slice lane>>3), shfl_xor reduce.
// Weights in SMEM [27][COUT][R], R=CIN+4 when per-lane slice %4==0 (LDS.128,
// 16B-aligned conflict-free rows), else CIN+1 scalar.
// EPI: 0 none; 1: out = xres - conv (8ch); 2: out = tile(xres) + conv (32ch).
// ---------------------------------------------------------------------------
template <int CIN, int COUT, int EPI, int TB, int MINB, int ILP>
__global__ void __launch_bounds__(TB, MINB)
conv_kernel(const float* __restrict__ in,
            const float* __restrict__ W,
            const float* __restrict__ xres,
            float* __restrict__ out, int N) {
    constexpr int csn = (COUT == 32) ? CIN : (CIN / 4);
    constexpr bool V4 = (csn & 3) == 0;
    constexpr int R   = V4 ? (CIN + 4) : (CIN + 1);
    extern __shared__ float Ws[];  // [27][COUT][R]

    const int tid = threadIdx.x;
    for (int i = tid; i < 27 * CIN * COUT; i += blockDim.x) {
        int k = i / (CIN * COUT);
        int rem = i % (CIN * COUT);
        int c = rem / COUT, j = rem % COUT;
        Ws[(k * COUT + j) * R + c] = W[i];
    }
    __syncthreads();

    const int lane = tid & 31;
    const int warp = tid >> 5;
    const int wpb  = blockDim.x >> 5;

    int oc, cs0;
    if (COUT == 32) { oc = lane; cs0 = 0; }
    else            { oc = lane & 7; cs0 = (lane >> 3) * csn; }

    float wc[csn];
#pragma unroll
    for (int c = 0; c < csn; c++)
        wc[c] = W[(13 * CIN + cs0 + c) * COUT + oc];

    const int gw      = blockIdx.x * wpb + warp;
    const int gstride = gridDim.x * wpb;

    for (int base = gw * ILP; base < N; base += gstride * ILP) {
        int4 L[ILP];
#pragma unroll
        for (int j = 0; j < ILP; j++) {
            int n = base + j;
            L[j] = (n < N)
                 ? *reinterpret_cast<const int4*>(&g_list[(size_t)n * LSTR])
                 : make_int4(0, 0, 0, 0);
        }
#pragma unroll
        for (int j = 0; j < ILP; j++) {
            const int n = base + j;
            if (n >= N) break;
            const int cnt = ((unsigned)L[j].x) >> 27;
            const float* xr = &in[(size_t)n * CIN];
            float acc0 = 0.f, acc1 = 0.f, acc2 = 0.f, acc3 = 0.f;

            // dense center tap (register weights)
            if constexpr (V4) {
                const float4* x4 = reinterpret_cast<const float4*>(xr + cs0);
#pragma unroll
                for (int c = 0; c < csn / 4; c++) {
                    float4 g = x4[c];
                    acc0 += g.x * wc[4 * c + 0];
                    acc1 += g.y * wc[4 * c + 1];
                    acc2 += g.z * wc[4 * c + 2];
                    acc3 += g.w * wc[4 * c + 3];
                }
            } else {
#pragma unroll
                for (int c = 0; c < csn; c++) acc0 += xr[cs0 + c] * wc[c];
            }

            auto do_entry = [&](int e) {
                const int k   = (e >> 20) & 31;
                const int src = e & 0xFFFFF;
                const float* grow = &in[(size_t)src * CIN + cs0];
                const float* wrow = &Ws[(k * COUT + oc) * R + cs0];
                if constexpr (V4) {
                    const float4* g4 = reinterpret_cast<const float4*>(grow);
                    const float4* w4 = reinterpret_cast<const float4*>(wrow);
#pragma unroll
                    for (int c = 0; c < csn / 4; c++) {
                        float4 g = g4[c];
                        float4 w = w4[c];
                        acc0 += g.x * w.x;
                        acc1 += g.y * w.y;
                        acc2 += g.z * w.z;
                        acc3 += g.w * w.w;
                    }
                } else {
#pragma unroll
                    for (int c = 0; c < csn; c++) acc0 += grow[c] * wrow[c];
                }
            };

            if (cnt > 0) do_entry(L[j].x);
            if (cnt > 1) do_entry(L[j].y);
            if (cnt > 2) do_entry(L[j].z);
            if (cnt > 3) do_entry(L[j].w);
#pragma unroll 1
            for (int i = 4; i < cnt; i++)
                do_entry(g_list[(size_t)n * LSTR + i]);

            float acc = (acc0 + acc1) + (acc2 + acc3);

            if constexpr (COUT == 8) {
                acc += __shfl_xor_sync(0xffffffffu, acc, 8);
                acc += __shfl_xor_sync(0xffffffffu, acc, 16);
                if (lane < 8) {
                    float v = acc;
                    if constexpr (EPI == 1) v = xres[(size_t)n * 8 + lane] - v;
                    out[(size_t)n * 8 + lane] = v;
                }
            } else {
                float v = acc;
                if constexpr (EPI == 2) v += xres[(size_t)n * 8 + (lane & 7)];
                out[(size_t)n * 32 + lane] = v;
            }
        }
    }
}

// ---------------------------------------------------------------------------
extern "C" void kernel_launch(void* const* d_in, const int* in_sizes, int n_in,
                              void* d_out, int out_size) {
    const float* x    = (const float*)d_in[0];
    const int*   nbr  = (const int*)d_in[1];
    const void*  mask = (const void*)d_in[2];
    const float* Wd0  = (const float*)d_in[3];
    const float* Wd1  = (const float*)d_in[4];
    const float* Wd2  = (const float*)d_in[5];
    const float* Wu0  = (const float*)d_in[6];
    const float* Wu1  = (const float*)d_in[7];
    const float* Wu2  = (const float*)d_in[8];
    float*       out  = (float*)d_out;
    const int N = in_sizes[0] / 8;

    float *t32, *t8a, *t8b, *wfold;
    cudaGetSymbolAddress((void**)&t32,   g_t32);
    cudaGetSymbolAddress((void**)&t8a,   g_t8a);
    cudaGetSymbolAddress((void**)&t8b,   g_t8b);
    cudaGetSymbolAddress((void**)&wfold, g_wfold);

    const int smem_8_32  = 27 * 32 * 12 * 4;   //  41,472 B (R=12)
    const int smem_32_8  = 27 * 8  * 36 * 4;   //  31,104 B (R=36)
    const int smem_8_8   = 27 * 8  * 9  * 4;   //   7,776 B (R=9)
    const int smem_32_32 = 27 * 32 * 36 * 4;   // 124,416 B (R=36)

    cudaFuncSetAttribute((const void*)conv_kernel<32, 32, 2, 1024, 1, 1>,
                         cudaFuncAttributeMaxDynamicSharedMemorySize,
                         smem_32_32);

    detect_mask<<<1, 256>>>((const unsigned int*)mask);
    build_compact<<<(N + 255) / 256, 256>>>(nbr, mask, N);
    fold_wd0<<<(27 * 8 * 32 + 255) / 256, 256>>>(Wd0);

    // K1: conv(tile(x), Wd0) == conv(x, wfold)   8 -> 32
    conv_kernel<8, 32, 0, 256, 5, 2><<<NSM * 5, 256, smem_8_32>>>(x, wfold, x, t32, N);
    // K2: 32 -> 8
    conv_kernel<32, 8, 0, 256, 6, 2><<<NSM * 6, 256, smem_32_8>>>(t32, Wd1, x, t8a, N);
    // K3: 8 -> 8, epilogue r0 = x - d
    conv_kernel<8, 8, 1, 256, 8, 2><<<NSM * 8, 256, smem_8_8>>>(t8a, Wd2, x, t8b, N);
    // K4: 8 -> 8
    conv_kernel<8, 8, 0, 256, 8, 2><<<NSM * 8, 256, smem_8_8>>>(t8b, Wu0, x, t8a, N);
    // K5: 8 -> 32
    conv_kernel<8, 32, 0, 256, 5, 2><<<NSM * 5, 256, smem_8_32>>>(t8a, Wu1, x, t32, N);
    // K6: 32 -> 32, epilogue out = tile(x) + conv   (124 KB smem -> 1 CTA/SM)
    conv_kernel<32, 32, 2, 1024, 1, 1><<<NSM, 1024, smem_32_32>>>(t32, Wu2, x, out, N);
}